// round 1
// baseline (speedup 1.0000x reference)
#include <cuda_runtime.h>
#include <math.h>
#include <stdint.h>

// ---------------- problem constants ----------------
#define B_      2
#define N_      2048
#define DIM_    1024
#define INNER_  512
#define HEADS_  8
#define DHEAD_  64
#define WS_     512
#define FF_     4096
#define BN_     (B_*N_)        // 4096
#define NP_     (N_+WS_)       // 2560 (padded rows: WS_ zero rows in front)
#define NWIN_   (N_/WS_)       // 4

// ---------------- scratch (device globals; no allocation allowed) ----------------
__device__ float g_at  [BN_*DIM_];          // audio_t (post LN)
__device__ float g_vt  [BN_*DIM_];          // video_t (post LN)
__device__ float g_qrot[BN_*DIM_];          // roped text
__device__ float g_krot[B_*NP_*DIM_];       // roped audio_t, zero-padded front WS_
__device__ float g_vpad[B_*NP_*DIM_];       // video_t, zero-padded front WS_
__device__ float g_probs[B_*NWIN_*WS_*2*WS_];
__device__ float g_x   [BN_*DIM_];          // local attn out -> ln1 (in place)
__device__ float g_q   [BN_*INNER_];
__device__ float g_kv  [BN_*2*INNER_];
__device__ float g_o   [BN_*INNER_];
__device__ float g_x2  [BN_*DIM_];          // 2*(o@Wo) (residual)
__device__ float g_ff  [BN_*FF_];

// ---------------- epilogue kinds ----------------
#define EPI_NONE       0
#define EPI_BIAS       1
#define EPI_BIAS_GELU  2
#define EPI_BIAS_RES   3

__device__ __forceinline__ float gelu_tanh(float v) {
    float c = v + 0.044715f * v * v * v;
    return 0.5f * v * (1.0f + tanhf(0.7978845608028654f * c));
}

// ---------------- SGEMM: C = alpha*A*B (+bias)(gelu)(+res) ----------------
// A[M,K] row-major. B: NN -> [K,N] row-major; NT -> [N,K] row-major (C=A*B^T).
// 128x128 tile, BK=8, 256 threads, 8x8 microtile. Strided batch via gridDim.z:
// z -> (zb=z/wdiv, zw=z%wdiv), pointer += zb*s?b + zw*s?w.
template<int EPI, bool TRANSB>
__global__ void __launch_bounds__(256)
sgemm_kernel(const float* __restrict__ A, const float* __restrict__ Bm,
             float* __restrict__ C,
             int M, int Nn, int K, float alpha,
             const float* __restrict__ bias, const float* __restrict__ res,
             int wdiv,
             long long sAb, long long sAw, long long sBb, long long sBw,
             long long sCb, long long sCw)
{
    int z  = blockIdx.z;
    int zb = z / wdiv, zw = z % wdiv;
    A  += zb * sAb + zw * sAw;
    Bm += zb * sBb + zw * sBw;
    C  += zb * sCb + zw * sCw;
    const float* R = (EPI == EPI_BIAS_RES) ? (res + zb * sCb + zw * sCw) : nullptr;

    __shared__ float As[8][128];
    __shared__ float Bs[8][128];

    int tid = threadIdx.x;
    int m0 = blockIdx.y * 128;
    int n0 = blockIdx.x * 128;

    // A tile load mapping (128x8): one float4 per thread
    int arow = tid >> 1;
    int acol = (tid & 1) * 4;
    const float* Aptr = A + (long long)(m0 + arow) * K + acol;

    int brow, bcol;
    const float* Bptr;
    if (TRANSB) { brow = tid >> 1; bcol = (tid & 1) * 4;
                  Bptr = Bm + (long long)(n0 + brow) * K + bcol; }
    else        { brow = tid >> 5; bcol = (tid & 31) * 4;
                  Bptr = Bm + (long long)brow * Nn + n0 + bcol; }

    float acc[8][8];
#pragma unroll
    for (int i = 0; i < 8; i++)
#pragma unroll
        for (int j = 0; j < 8; j++) acc[i][j] = 0.f;

    int ty = tid >> 4, tx = tid & 15;

    float4 aReg = *(const float4*)Aptr;
    float4 bReg = *(const float4*)Bptr;

    int ktiles = K >> 3;
    for (int kt = 0; kt < ktiles; kt++) {
        As[acol + 0][arow] = aReg.x;
        As[acol + 1][arow] = aReg.y;
        As[acol + 2][arow] = aReg.z;
        As[acol + 3][arow] = aReg.w;
        if (TRANSB) {
            Bs[bcol + 0][brow] = bReg.x;
            Bs[bcol + 1][brow] = bReg.y;
            Bs[bcol + 2][brow] = bReg.z;
            Bs[bcol + 3][brow] = bReg.w;
        } else {
            *(float4*)&Bs[brow][bcol] = bReg;
        }
        __syncthreads();

        if (kt + 1 < ktiles) {
            Aptr += 8;
            aReg = *(const float4*)Aptr;
            if (TRANSB) Bptr += 8;
            else        Bptr += (long long)8 * Nn;
            bReg = *(const float4*)Bptr;
        }

#pragma unroll
        for (int kk = 0; kk < 8; kk++) {
            float a[8], bf[8];
            *(float4*)&a[0]  = *(const float4*)&As[kk][ty * 4];
            *(float4*)&a[4]  = *(const float4*)&As[kk][ty * 4 + 64];
            *(float4*)&bf[0] = *(const float4*)&Bs[kk][tx * 4];
            *(float4*)&bf[4] = *(const float4*)&Bs[kk][tx * 4 + 64];
#pragma unroll
            for (int i = 0; i < 8; i++)
#pragma unroll
                for (int j = 0; j < 8; j++)
                    acc[i][j] += a[i] * bf[j];
        }
        __syncthreads();
    }

    // epilogue
#pragma unroll
    for (int i = 0; i < 8; i++) {
        int row = m0 + ty * 4 + ((i & 4) ? 64 : 0) + (i & 3);
#pragma unroll
        for (int jg = 0; jg < 2; jg++) {
            int col = n0 + tx * 4 + jg * 64;
            float o0 = acc[i][jg * 4 + 0] * alpha;
            float o1 = acc[i][jg * 4 + 1] * alpha;
            float o2 = acc[i][jg * 4 + 2] * alpha;
            float o3 = acc[i][jg * 4 + 3] * alpha;
            if (EPI != EPI_NONE) {
                float4 bb = *(const float4*)&bias[col];
                o0 += bb.x; o1 += bb.y; o2 += bb.z; o3 += bb.w;
            }
            if (EPI == EPI_BIAS_GELU) {
                o0 = gelu_tanh(o0); o1 = gelu_tanh(o1);
                o2 = gelu_tanh(o2); o3 = gelu_tanh(o3);
            }
            if (EPI == EPI_BIAS_RES) {
                float4 rr = *(const float4*)&R[(long long)row * Nn + col];
                o0 += rr.x; o1 += rr.y; o2 += rr.z; o3 += rr.w;
            }
            float4 vv = make_float4(o0, o1, o2, o3);
            *(float4*)&C[(long long)row * Nn + col] = vv;
        }
    }
}

// ---------------- LayerNorm (block per row, row cached in smem) ----------------
__global__ void ln_kernel(const float* __restrict__ x, float* __restrict__ y,
                          const float* __restrict__ g, const float* __restrict__ bv,
                          int L)
{
    __shared__ float buf[4096];
    __shared__ float r1[8], r2[8];
    __shared__ float stats[2];
    long long row = blockIdx.x;
    const float* xr = x + row * L;
    int tid = threadIdx.x;
    float s = 0.f, s2 = 0.f;
    for (int c = tid; c < L; c += 256) {
        float v = xr[c];
        buf[c] = v; s += v; s2 += v * v;
    }
#pragma unroll
    for (int o = 16; o > 0; o >>= 1) {
        s  += __shfl_xor_sync(0xffffffffu, s,  o);
        s2 += __shfl_xor_sync(0xffffffffu, s2, o);
    }
    int lane = tid & 31, w = tid >> 5;
    if (lane == 0) { r1[w] = s; r2[w] = s2; }
    __syncthreads();
    if (tid == 0) {
        float ts = 0.f, ts2 = 0.f;
        for (int k = 0; k < 8; k++) { ts += r1[k]; ts2 += r2[k]; }
        float mean = ts / (float)L;
        float var  = ts2 / (float)L - mean * mean;
        stats[0] = mean;
        stats[1] = rsqrtf(var + 1e-5f);
    }
    __syncthreads();
    float mean = stats[0], rstd = stats[1];
    float* yr = y + row * L;
    for (int c = tid; c < L; c += 256)
        yr[c] = (buf[c] - mean) * rstd * g[c] + bv[c];
}

// ---------------- RMSNorm over 64-dim head vectors (warp per vector) ----------------
__global__ void rms_kernel(float* __restrict__ x, const float* __restrict__ g,
                           int vecs_per_row, int row_stride, int nrows)
{
    int vid  = blockIdx.x * 8 + (threadIdx.x >> 5);
    int lane = threadIdx.x & 31;
    int r = vid / vecs_per_row;
    int h = vid - r * vecs_per_row;
    if (r >= nrows) return;
    float* p = x + (long long)r * row_stride + h * DHEAD_;
    float v0 = p[lane], v1 = p[lane + 32];
    float ss = v0 * v0 + v1 * v1;
#pragma unroll
    for (int o = 16; o > 0; o >>= 1) ss += __shfl_xor_sync(0xffffffffu, ss, o);
    float rs = rsqrtf(ss * (1.0f / 64.0f) + 1e-6f);
    p[lane]      = v0 * rs * g[lane];
    p[lane + 32] = v1 * rs * g[lane + 32];
}

// ---------------- rotary + padded-copy prep ----------------
// Writes g_qrot (roped text), g_krot (roped audio_t into padded layout),
// g_vpad (video_t into padded layout), zeros the WS_ front pad rows.
__global__ void prep_kernel(const float* __restrict__ text,
                            const float* __restrict__ at,
                            const float* __restrict__ vt)
{
    int row = blockIdx.x;               // 0 .. B_*NP_-1
    int b = row / NP_;
    int pr = row - b * NP_;
    float* kd = g_krot + (long long)row * DIM_;
    float* vd = g_vpad + (long long)row * DIM_;
    if (pr < WS_) {
        for (int c = threadIdx.x; c < DIM_; c += 256) { kd[c] = 0.f; vd[c] = 0.f; }
        return;
    }
    int t = pr - WS_;
    long long src = ((long long)b * N_ + t) * DIM_;
    float* qd = g_qrot + src;
    for (int c = threadIdx.x; c < DIM_; c += 256) {
        int j = c & 511;
        float e = (float)j * (1.0f / 512.0f);
        float invf = 1.0f / powf(10000.0f, e);
        float ang = (float)t * invf;
        float cs = cosf(ang), sn = sinf(ang);
        float kx = at[src + c];
        float ko = (c < 512) ? -at[src + c + 512] : at[src + c - 512];
        kd[c] = kx * cs + ko * sn;
        float qx = text[src + c];
        float qo = (c < 512) ? -text[src + c + 512] : text[src + c - 512];
        qd[c] = qx * cs + qo * sn;
        vd[c] = vt[src + c];
    }
}

// ---------------- local-attention masked softmax (block per row of 1024) -------
__global__ void softmax_local_kernel(float* __restrict__ p)
{
    int r = blockIdx.x;                 // 0 .. B_*NWIN_*WS_-1
    int i = r & (WS_ - 1);
    int z = r >> 9;
    int w = z & (NWIN_ - 1);
    int qp = w * WS_ + i;
    float* row = p + (long long)r * (2 * WS_);
    int tid = threadIdx.x, lane = tid & 31, warp = tid >> 5;
    __shared__ float smax[8], ssum[8], bcast[2];

    float mx = -1e30f;
    for (int j = tid; j < 2 * WS_; j += 256) {
        int kp = (w - 1) * WS_ + j;
        float v = (kp >= 0 && kp <= qp) ? row[j] : -1e9f;
        row[j] = v;
        mx = fmaxf(mx, v);
    }
#pragma unroll
    for (int o = 16; o > 0; o >>= 1) mx = fmaxf(mx, __shfl_xor_sync(0xffffffffu, mx, o));
    if (lane == 0) smax[warp] = mx;
    __syncthreads();
    if (tid == 0) {
        float m = smax[0];
        for (int k = 1; k < 8; k++) m = fmaxf(m, smax[k]);
        bcast[0] = m;
    }
    __syncthreads();
    mx = bcast[0];

    float sum = 0.f;
    for (int j = tid; j < 2 * WS_; j += 256) {
        float e = __expf(row[j] - mx);
        row[j] = e; sum += e;
    }
#pragma unroll
    for (int o = 16; o > 0; o >>= 1) sum += __shfl_xor_sync(0xffffffffu, sum, o);
    if (lane == 0) ssum[warp] = sum;
    __syncthreads();
    if (tid == 0) {
        float t = 0.f;
        for (int k = 0; k < 8; k++) t += ssum[k];
        bcast[1] = 1.0f / t;
    }
    __syncthreads();
    float inv = bcast[1];
    for (int j = tid; j < 2 * WS_; j += 256) row[j] *= inv;
}

// ---------------- causal flash attention (per head, D=64) ----------------
// grid = (N_/64, B_*HEADS_), 256 threads. 64q x 64k tiles, online softmax.
// Smem tiles stored k-index-major (transposed) so inner loops use float4 LDS.
#define QP_ 68
#define ATTN_SMEM_BYTES (4 * 64 * QP_ * 4 + 3 * 64 * 4)

__global__ void __launch_bounds__(256)
attn_kernel(const float* __restrict__ q, const float* __restrict__ kv,
            float* __restrict__ o)
{
    extern __shared__ float sm[];
    float* QsT = sm;                    // [d=64][QP_] : QsT[c*QP_+r]
    float* KsT = QsT + 64 * QP_;        // [d=64][QP_] : KsT[c*QP_+r]  (r = key)
    float* Vs  = KsT + 64 * QP_;        // [key][QP_]  : Vs[r*QP_+c]
    float* SsT = Vs  + 64 * QP_;        // [key][QP_]  : S^T / P^T
    float* Ms = SsT + 64 * QP_;
    float* Ls = Ms + 64;
    float* Cs = Ls + 64;

    int tid = threadIdx.x;
    int bh = blockIdx.y;
    int b = bh >> 3, h = bh & 7;
    int q0 = blockIdx.x * 64;
    int ty = tid >> 4, tx = tid & 15;

    for (int idx = tid; idx < 4096; idx += 256) {
        int r = idx >> 6, c = idx & 63;
        QsT[c * QP_ + r] =
            q[((long long)(b * N_ + q0 + r)) * INNER_ + h * 64 + c] * 0.125f;
    }
    if (tid < 64) { Ms[tid] = -INFINITY; Ls[tid] = 0.f; }
    float oacc[16];
#pragma unroll
    for (int i = 0; i < 16; i++) oacc[i] = 0.f;
    __syncthreads();

    int lastTile = blockIdx.x;
    for (int kt = 0; kt <= lastTile; kt++) {
        for (int idx = tid; idx < 4096; idx += 256) {
            int r = idx >> 6, c = idx & 63;
            long long base =
                ((long long)(b * N_ + kt * 64 + r)) * (2 * INNER_) + h * 64 + c;
            KsT[c * QP_ + r] = kv[base];
            Vs[r * QP_ + c]  = kv[base + INNER_];
        }
        __syncthreads();

        float sacc[16];
#pragma unroll
        for (int i = 0; i < 16; i++) sacc[i] = 0.f;
#pragma unroll 8
        for (int kk = 0; kk < 64; kk++) {
            float4 aq = *(const float4*)&QsT[kk * QP_ + ty * 4];
            float4 bk = *(const float4*)&KsT[kk * QP_ + tx * 4];
            float a4[4] = {aq.x, aq.y, aq.z, aq.w};
            float b4[4] = {bk.x, bk.y, bk.z, bk.w};
#pragma unroll
            for (int i = 0; i < 4; i++)
#pragma unroll
                for (int j = 0; j < 4; j++)
                    sacc[i * 4 + j] += a4[i] * b4[j];
        }
        bool diag = (kt == lastTile);
#pragma unroll
        for (int i = 0; i < 4; i++)
#pragma unroll
            for (int j = 0; j < 4; j++) {
                int qr = ty * 4 + i, kc = tx * 4 + j;
                float s = sacc[i * 4 + j];
                if (diag && kc > qr) s = -INFINITY;
                SsT[kc * QP_ + qr] = s;
            }
        __syncthreads();

        if (tid < 64) {
            int r = tid;
            float mt = -INFINITY;
#pragma unroll 8
            for (int c = 0; c < 64; c++) mt = fmaxf(mt, SsT[c * QP_ + r]);
            float mo = Ms[r];
            float mn = fmaxf(mo, mt);
            float corr = __expf(mo - mn);
            float ls = 0.f;
#pragma unroll 8
            for (int c = 0; c < 64; c++) {
                float e = __expf(SsT[c * QP_ + r] - mn);
                SsT[c * QP_ + r] = e;
                ls += e;
            }
            Ls[r] = Ls[r] * corr + ls;
            Ms[r] = mn;
            Cs[r] = corr;
        }
        __syncthreads();

        float cf[4];
#pragma unroll
        for (int i = 0; i < 4; i++) cf[i] = Cs[ty * 4 + i];
#pragma unroll
        for (int i = 0; i < 4; i++)
#pragma unroll
            for (int j = 0; j < 4; j++) oacc[i * 4 + j] *= cf[i];

#pragma unroll 8
        for (int kk = 0; kk < 64; kk++) {
            float4 ap = *(const float4*)&SsT[kk * QP_ + ty * 4];
            float4 vv = *(const float4*)&Vs[kk * QP_ + tx * 4];
            float a4[4] = {ap.x, ap.y, ap.z, ap.w};
            float b4[4] = {vv.x, vv.y, vv.z, vv.w};
#pragma unroll
            for (int i = 0; i < 4; i++)
#pragma unroll
                for (int j = 0; j < 4; j++)
                    oacc[i * 4 + j] += a4[i] * b4[j];
        }
        __syncthreads();
    }

#pragma unroll
    for (int i = 0; i < 4; i++) {
        float inv = 1.0f / Ls[ty * 4 + i];
        long long orow =
            ((long long)(b * N_ + q0 + ty * 4 + i)) * INNER_ + h * 64 + tx * 4;
        float4 vo = make_float4(oacc[i * 4 + 0] * inv, oacc[i * 4 + 1] * inv,
                                oacc[i * 4 + 2] * inv, oacc[i * 4 + 3] * inv);
        *(float4*)&o[orow] = vo;
    }
}

// ---------------- launch ----------------
extern "C" void kernel_launch(void* const* d_in, const int* in_sizes, int n_in,
                              void* d_out, int out_size)
{
    (void)in_sizes; (void)n_in; (void)out_size;
    const float* text  = (const float*)d_in[0];
    const float* audio = (const float*)d_in[1];
    const float* video = (const float*)d_in[2];
    const float* Wa    = (const float*)d_in[3];
    const float* ba    = (const float*)d_in[4];
    const float* lna_g = (const float*)d_in[5];
    const float* lna_b = (const float*)d_in[6];
    const float* Wvid  = (const float*)d_in[7];
    const float* bvid  = (const float*)d_in[8];
    const float* lnv_g = (const float*)d_in[9];
    const float* lnv_b = (const float*)d_in[10];
    const float* ln1_g = (const float*)d_in[11];
    const float* ln1_b = (const float*)d_in[12];
    const float* Wq    = (const float*)d_in[13];
    const float* Wkv   = (const float*)d_in[14];
    const float* qn_g  = (const float*)d_in[15];
    const float* kn_g  = (const float*)d_in[16];
    const float* Wo    = (const float*)d_in[17];
    const float* W1    = (const float*)d_in[18];
    const float* b1    = (const float*)d_in[19];
    const float* ln2_g = (const float*)d_in[20];
    const float* ln2_b = (const float*)d_in[21];
    const float* W2    = (const float*)d_in[22];
    const float* b2    = (const float*)d_in[23];
    float* out = (float*)d_out;

    float *at, *vt, *qrot, *krot, *vpad, *probs, *x, *qb, *kvb, *ob, *x2, *ff;
    cudaGetSymbolAddress((void**)&at,   g_at);
    cudaGetSymbolAddress((void**)&vt,   g_vt);
    cudaGetSymbolAddress((void**)&qrot, g_qrot);
    cudaGetSymbolAddress((void**)&krot, g_krot);
    cudaGetSymbolAddress((void**)&vpad, g_vpad);
    cudaGetSymbolAddress((void**)&probs,g_probs);
    cudaGetSymbolAddress((void**)&x,    g_x);
    cudaGetSymbolAddress((void**)&qb,   g_q);
    cudaGetSymbolAddress((void**)&kvb,  g_kv);
    cudaGetSymbolAddress((void**)&ob,   g_o);
    cudaGetSymbolAddress((void**)&x2,   g_x2);
    cudaGetSymbolAddress((void**)&ff,   g_ff);

    cudaFuncSetAttribute(attn_kernel,
                         cudaFuncAttributeMaxDynamicSharedMemorySize,
                         ATTN_SMEM_BYTES);

    dim3 blk(256);

    // 1) adapters: linear + bias, then LayerNorm
    sgemm_kernel<EPI_BIAS, false><<<dim3(DIM_/128, BN_/128, 1), blk>>>(
        audio, Wa, at, BN_, DIM_, DIM_, 1.f, ba, nullptr, 1, 0,0,0,0,0,0);
    sgemm_kernel<EPI_BIAS, false><<<dim3(DIM_/128, BN_/128, 1), blk>>>(
        video, Wvid, vt, BN_, DIM_, DIM_, 1.f, bvid, nullptr, 1, 0,0,0,0,0,0);
    ln_kernel<<<BN_, 256>>>(at, at, lna_g, lna_b, DIM_);
    ln_kernel<<<BN_, 256>>>(vt, vt, lnv_g, lnv_b, DIM_);

    // 2) rotary + padded k/v layout
    prep_kernel<<<B_ * NP_, 256>>>(text, at, vt);

    // 3) local attention: sim = (q/32) @ k^T  (batched over 8 (b,w) windows)
    sgemm_kernel<EPI_NONE, true><<<dim3((2*WS_)/128, WS_/128, B_*NWIN_), blk>>>(
        qrot, krot, probs, WS_, 2*WS_, DIM_, 0.03125f, nullptr, nullptr,
        NWIN_,
        (long long)N_ * DIM_,  (long long)WS_ * DIM_,
        (long long)NP_ * DIM_, (long long)WS_ * DIM_,
        (long long)NWIN_ * WS_ * 2 * WS_, (long long)WS_ * 2 * WS_);
    softmax_local_kernel<<<B_ * NWIN_ * WS_, 256>>>(probs);
    sgemm_kernel<EPI_NONE, false><<<dim3(DIM_/128, WS_/128, B_*NWIN_), blk>>>(
        probs, vpad, x, WS_, DIM_, 2*WS_, 1.f, nullptr, nullptr,
        NWIN_,
        (long long)NWIN_ * WS_ * 2 * WS_, (long long)WS_ * 2 * WS_,
        (long long)NP_ * DIM_, (long long)WS_ * DIM_,
        (long long)N_ * DIM_,  (long long)WS_ * DIM_);

    // 4) ln1 -> q / kv projections -> qk rmsnorm
    ln_kernel<<<BN_, 256>>>(x, x, ln1_g, ln1_b, DIM_);
    sgemm_kernel<EPI_NONE, false><<<dim3(INNER_/128, BN_/128, 1), blk>>>(
        x, Wq, qb, BN_, INNER_, DIM_, 1.f, nullptr, nullptr, 1, 0,0,0,0,0,0);
    sgemm_kernel<EPI_NONE, false><<<dim3((2*INNER_)/128, BN_/128, 1), blk>>>(
        x, Wkv, kvb, BN_, 2*INNER_, DIM_, 1.f, nullptr, nullptr, 1, 0,0,0,0,0,0);
    rms_kernel<<<(BN_ * HEADS_) / 8, 256>>>(qb, qn_g, HEADS_, INNER_, BN_);
    rms_kernel<<<(BN_ * HEADS_) / 8, 256>>>(kvb, kn_g, HEADS_, 2*INNER_, BN_);

    // 5) causal attention
    attn_kernel<<<dim3(N_/64, B_*HEADS_), 256, ATTN_SMEM_BYTES>>>(qb, kvb, ob);

    // 6) x = 2*(o @ Wo)
    sgemm_kernel<EPI_NONE, false><<<dim3(DIM_/128, BN_/128, 1), blk>>>(
        ob, Wo, x2, BN_, DIM_, INNER_, 2.f, nullptr, nullptr, 1, 0,0,0,0,0,0);

    // 7) FFN: gelu(x@W1+b1) -> LN -> @W2 + b2 + x
    sgemm_kernel<EPI_BIAS_GELU, false><<<dim3(FF_/128, BN_/128, 1), blk>>>(
        x2, W1, ff, BN_, FF_, DIM_, 1.f, b1, nullptr, 1, 0,0,0,0,0,0);
    ln_kernel<<<BN_, 256>>>(ff, ff, ln2_g, ln2_b, FF_);
    sgemm_kernel<EPI_BIAS_RES, false><<<dim3(DIM_/128, BN_/128, 1), blk>>>(
        ff, W2, out, BN_, DIM_, FF_, 1.f, b2, x2, 1, 0,0,0,0,0,0);
}